// round 3
// baseline (speedup 1.0000x reference)
#include <cuda_runtime.h>
#include <math.h>

#define L 64
#define R 4096
#define E 32
#define F 64
#define P 8

// ---- GEMM tiling ----
#define RT_A   128
#define NRT_A  (R / RT_A)    // 32

// ---- RBF tiling ----
#define RTILE 256
#define NRT   (R / RTILE)    // 16

// RBF constants
#define DELTA      (10.0f / 31.0f)
#define INV_DELTA  (31.0f / 10.0f)
// KC = sqrt(log2(e)) / |sigma|, sigma = -0.3125 -> exp(-z^2) = exp2(-(KC*(d-mu))^2)
#define KC         3.8435917081166394f
#define DK         (DELTA * KC)
#define WIN        2.0f      // |d-mu| > WIN -> rbf < 2e-18, safely dropped

typedef unsigned long long ull;

// scratch: atn[e][l][r] (33.5 MB, L2-resident) and per-block partials
__device__ float g_atn[E * L * R];
__device__ float g_part[L * NRT * P];

__device__ __forceinline__ ull pk2(float x) {
    ull r;
    asm("mov.b64 %0, {%1, %1};" : "=l"(r) : "f"(x));
    return r;
}
__device__ __forceinline__ void fma2(ull& d, ull a, ull b) {
    asm("fma.rn.f32x2 %0, %1, %2, %0;" : "+l"(d) : "l"(a), "l"(b));
}

// ---------------------------------------------------------------------------
// Kernel A: atn[e][l][r] = sum_f lig[l][e][f] * rec[r][e][f]
// grid (E, NRT_A), 256 threads. C-tile 64l x 128r, micro-tile 8l x 4r (2x f32x2)
// smem (f-major): s_lig[f][l] 16KB, s_rec[f][r] 32KB.
//   a-loads: warp-uniform LDS.128 broadcast; b-loads: conflict-free LDS.64.
// Inner f-step: 4 LDS + 16 FFMA2  (128 FMA lanes / ~20 issues)
// ---------------------------------------------------------------------------
__global__ __launch_bounds__(256, 2) void atn_gemm(const float* __restrict__ lig,
                                                   const float* __restrict__ rec) {
    const int e  = blockIdx.x;
    const int rt = blockIdx.y * RT_A;
    extern __shared__ float sm[];
    float* s_lig = sm;                 // [64 f][64 l]
    float* s_rec = sm + 64 * 64;       // [64 f][128 r]
    const int tid = threadIdx.x;

    // load lig[:, e, :] (4096 floats), transpose to f-major
#pragma unroll
    for (int k = 0; k < 4; k++) {
        int idx = tid + (k << 8);           // float4 index
        int l = idx >> 4, f4 = idx & 15;
        float4 v = *(const float4*)(lig + ((l * E + e) << 6) + (f4 << 2));
        int f = f4 << 2;
        s_lig[(f + 0) * 64 + l] = v.x;
        s_lig[(f + 1) * 64 + l] = v.y;
        s_lig[(f + 2) * 64 + l] = v.z;
        s_lig[(f + 3) * 64 + l] = v.w;
    }
    // load rec[rt:rt+128, e, :] (8192 floats), transpose to f-major
#pragma unroll
    for (int k = 0; k < 8; k++) {
        int idx = tid + (k << 8);
        int rl = idx >> 4, f4 = idx & 15;
        float4 v = *(const float4*)(rec + (((rt + rl) * E + e) << 6) + (f4 << 2));
        int f = f4 << 2;
        s_rec[(f + 0) * 128 + rl] = v.x;
        s_rec[(f + 1) * 128 + rl] = v.y;
        s_rec[(f + 2) * 128 + rl] = v.z;
        s_rec[(f + 3) * 128 + rl] = v.w;
    }
    __syncthreads();

    const int ly = tid >> 5;   // warp-uniform: a-loads broadcast
    const int rx = tid & 31;   // r pairs: {2*rx, 2*rx+1} and {+64, +65}

    ull c[8][2];
#pragma unroll
    for (int i = 0; i < 8; i++) { c[i][0] = 0ull; c[i][1] = 0ull; }

    const float* pa = s_lig + (ly << 3);
    const float* pb = s_rec + (rx << 1);

#pragma unroll 2
    for (int f = 0; f < F; f++) {
        float4 a0 = *(const float4*)(pa + f * 64);
        float4 a1 = *(const float4*)(pa + f * 64 + 4);
        ull b0 = *(const ull*)(pb + f * 128);
        ull b1 = *(const ull*)(pb + f * 128 + 64);
        ull aa;
        aa = pk2(a0.x); fma2(c[0][0], aa, b0); fma2(c[0][1], aa, b1);
        aa = pk2(a0.y); fma2(c[1][0], aa, b0); fma2(c[1][1], aa, b1);
        aa = pk2(a0.z); fma2(c[2][0], aa, b0); fma2(c[2][1], aa, b1);
        aa = pk2(a0.w); fma2(c[3][0], aa, b0); fma2(c[3][1], aa, b1);
        aa = pk2(a1.x); fma2(c[4][0], aa, b0); fma2(c[4][1], aa, b1);
        aa = pk2(a1.y); fma2(c[5][0], aa, b0); fma2(c[5][1], aa, b1);
        aa = pk2(a1.z); fma2(c[6][0], aa, b0); fma2(c[6][1], aa, b1);
        aa = pk2(a1.w); fma2(c[7][0], aa, b0); fma2(c[7][1], aa, b1);
    }

#pragma unroll
    for (int i = 0; i < 8; i++) {
        int l = (ly << 3) + i;
        float* base = g_atn + ((e << 6) + l) * R + rt + (rx << 1);
        *(ull*)(base)      = c[i][0];
        *(ull*)(base + 64) = c[i][1];
    }
}

// ---------------------------------------------------------------------------
// Kernel B: windowed RBF accumulation.
// grid (L, NRT), 256 threads; thread <-> one r; 8 poses; e-window <= 13.
// ---------------------------------------------------------------------------
__global__ __launch_bounds__(256) void rbf_energy(const float* __restrict__ ligc,
                                                  const float* __restrict__ recc) {
    const int l   = blockIdx.x;
    const int rt  = blockIdx.y * RTILE;
    const int tid = threadIdx.x;

    __shared__ float s_a[E][256];   // atn tile, dynamic-e indexable
    __shared__ float s_lc[P][3];
    __shared__ float s_red[8][P];

    if (tid < P * 3) {
        int p = tid / 3, cc = tid % 3;
        s_lc[p][cc] = ligc[p * (L * 3) + l * 3 + cc];
    }
#pragma unroll
    for (int e = 0; e < E; e++)
        s_a[e][tid] = g_atn[(e * L + l) * R + rt + tid];
    __syncthreads();

    const int r = rt + tid;
    const float cx = recc[3 * r + 0];
    const float cy = recc[3 * r + 1];
    const float cz = recc[3 * r + 2];

    float acc[P];
#pragma unroll
    for (int p = 0; p < P; p++) {
        float dx = s_lc[p][0] - cx;
        float dy = s_lc[p][1] - cy;
        float dz = s_lc[p][2] - cz;
        // eps added per-coordinate before sum, as in reference: +3*1e-10
        float d2 = fmaf(dx, dx, fmaf(dy, dy, fmaf(dz, dz, 3.0e-10f)));
        float d  = sqrtf(d2);

        int elo = (int)ceilf((d - WIN) * INV_DELTA);
        if (elo < 0) elo = 0;
        int ehi = (int)floorf((d + WIN) * INV_DELTA);
        if (ehi > E - 1) ehi = E - 1;

        float s  = (d - (float)elo * DELTA) * KC;
        float ap = 0.0f;
        for (int e = elo; e <= ehi; e++) {
            float t = -s * s;
            float rbf;
            asm("ex2.approx.ftz.f32 %0, %1;" : "=f"(rbf) : "f"(t));
            ap = fmaf(s_a[e][tid], rbf, ap);
            s -= DK;
        }
        acc[p] = ap;
    }

    // deterministic block reduction
#pragma unroll
    for (int p = 0; p < P; p++) {
        float v = acc[p];
#pragma unroll
        for (int off = 16; off; off >>= 1)
            v += __shfl_down_sync(0xffffffffu, v, off);
        if ((tid & 31) == 0) s_red[tid >> 5][p] = v;
    }
    __syncthreads();
    if (tid < P) {
        float v = 0.0f;
#pragma unroll
        for (int w = 0; w < 8; w++) v += s_red[w][tid];
        g_part[(l * NRT + blockIdx.y) * P + tid] = v;
    }
}

// ---------------------------------------------------------------------------
// Kernel C: reduce partials, apply weight/bias
// ---------------------------------------------------------------------------
__global__ __launch_bounds__(256) void finalize_k(const float* __restrict__ w,
                                                  const float* __restrict__ b,
                                                  float* __restrict__ out) {
    const int p    = threadIdx.x >> 5;   // 8 warps -> 8 poses
    const int lane = threadIdx.x & 31;
    float s = 0.0f;
    for (int k = lane; k < L * NRT; k += 32) s += g_part[k * P + p];
#pragma unroll
    for (int off = 16; off; off >>= 1)
        s += __shfl_down_sync(0xffffffffu, s, off);
    if (lane == 0) out[p] = fmaf(s, *w, *b);
}

// ---------------------------------------------------------------------------
extern "C" void kernel_launch(void* const* d_in, const int* in_sizes, int n_in,
                              void* d_out, int out_size) {
    const float* lig_feat   = (const float*)d_in[0];
    const float* rec_feat   = (const float*)d_in[1];
    const float* lig_coords = (const float*)d_in[2];
    const float* rec_coord  = (const float*)d_in[3];
    const float* weight     = (const float*)d_in[4];
    const float* bias       = (const float*)d_in[5];
    float* out = (float*)d_out;

    const int smem = (64 * 64 + 64 * 128) * (int)sizeof(float);  // 48 KB
    cudaFuncSetAttribute(atn_gemm, cudaFuncAttributeMaxDynamicSharedMemorySize, smem);

    atn_gemm  <<<dim3(E, NRT_A), 256, smem>>>(lig_feat, rec_feat);
    rbf_energy<<<dim3(L, NRT), 256>>>(lig_coords, rec_coord);
    finalize_k<<<1, 256>>>(weight, bias, out);
}

// round 8
// speedup vs baseline: 1.3931x; 1.3931x over previous
#include <cuda_runtime.h>
#include <math.h>
#include <cstdint>

#define L 64
#define R 4096
#define E 32
#define F 64
#define P 8

// ---- GEMM tiling: per block e fixed, M(r)=128, N(l)=64, K(f)=64 ----
#define MT     128
#define NRT_A  (R / MT)      // 32
#define SA     68            // smem row stride (floats): (68*g+t)%32 = 4g+t, conflict-free

// ---- RBF tiling ----
#define RTILE 256
#define NRT   (R / RTILE)    // 16

// RBF constants
#define DELTA      (10.0f / 31.0f)
#define INV_DELTA  (31.0f / 10.0f)
#define KC         3.8435917081166394f   // sqrt(log2 e)/|sigma|, sigma = -0.3125
#define DK         (DELTA * KC)
#define WIN        2.0f                   // |d-mu| > 2 -> rbf < 2e-18, dropped

// scratch: atn[e][l][r] (33.5 MB, L2-resident) and per-block partials
__device__ float g_atn[E * L * R];
__device__ float g_part[L * NRT * P];

__device__ __forceinline__ uint32_t tf32_rna(float x) {
    uint32_t r;
    asm("cvt.rna.tf32.f32 %0, %1;" : "=r"(r) : "f"(x));
    return r;
}
__device__ __forceinline__ void split_tf32(float x, uint32_t& hi, uint32_t& lo) {
    hi = tf32_rna(x);
    lo = tf32_rna(x - __uint_as_float(hi));
}
__device__ __forceinline__ void mma_tf32(float* d, const uint32_t* a,
                                         uint32_t b0, uint32_t b1) {
    asm volatile(
        "mma.sync.aligned.m16n8k8.row.col.f32.tf32.tf32.f32 "
        "{%0,%1,%2,%3}, {%4,%5,%6,%7}, {%8,%9}, {%0,%1,%2,%3};"
        : "+f"(d[0]), "+f"(d[1]), "+f"(d[2]), "+f"(d[3])
        : "r"(a[0]), "r"(a[1]), "r"(a[2]), "r"(a[3]), "r"(b0), "r"(b1));
}

// ---------------------------------------------------------------------------
// Kernel A: 3xTF32 mma.sync.  atn_t[r, l] = sum_f rec[r,e,f] * lig[l,e,f]
// grid (E, NRT_A), 256 threads (8 warps). Warp w: rows m0=16w..m0+15, all 64 l.
// smem: fp32 tiles s_rec[128][SA], s_lig[64][SA]; hi/lo split done in regs.
// Fragment maps (PTX ISA m16n8k8, row.col):
//   A: a0=A[g][t] a1=A[g+8][t] a2=A[g][t+4] a3=A[g+8][t+4]
//   B: b0=B[k=t][n=g] b1=B[k=t+4][n=g]   (col-major: n-row, k-col in s_lig)
//   C: c0=(g,2t) c1=(g,2t+1) c2=(g+8,2t) c3=(g+8,2t+1)
// ---------------------------------------------------------------------------
__global__ __launch_bounds__(256)
void atn_mma(const float* __restrict__ lig, const float* __restrict__ rec) {
    extern __shared__ float sm[];
    float* s_rec = sm;              // 128*SA
    float* s_lig = sm + 128 * SA;   // 64*SA
    const int e   = blockIdx.x;
    const int rt  = blockIdx.y * MT;
    const int tid = threadIdx.x;

    // ---- load rec tile [128 r][64 f] ----
#pragma unroll
    for (int it = 0; it < 8; it++) {
        int idx = tid + (it << 8);         // float4 index
        int row = idx >> 4, f4 = idx & 15;
        float4 v = *(const float4*)(rec + (((rt + row) * E + e) << 6) + (f4 << 2));
        *(float4*)(s_rec + row * SA + (f4 << 2)) = v;
    }
    // ---- load lig tile [64 l][64 f] ----
#pragma unroll
    for (int it = 0; it < 4; it++) {
        int idx = tid + (it << 8);
        int row = idx >> 4, f4 = idx & 15;
        float4 v = *(const float4*)(lig + ((row * E + e) << 6) + (f4 << 2));
        *(float4*)(s_lig + row * SA + (f4 << 2)) = v;
    }
    __syncthreads();

    const int wid = tid >> 5;
    const int lid = tid & 31;
    const int g   = lid >> 2;      // group id (0..7)
    const int t   = lid & 3;       // thread in group (0..3)
    const int m0  = wid << 4;      // 16-row tile per warp

    float d[8][4];
#pragma unroll
    for (int j = 0; j < 8; j++)
#pragma unroll
        for (int c = 0; c < 4; c++) d[j][c] = 0.0f;

    const float* pa = s_rec + (m0 + g) * SA + t;
    const float* pb = s_lig + g * SA + t;

#pragma unroll
    for (int ks = 0; ks < 8; ks++) {
        const int k0 = ks << 3;
        // A fragment (fp32) -> hi/lo tf32
        float af0 = pa[k0];
        float af1 = pa[8 * SA + k0];
        float af2 = pa[k0 + 4];
        float af3 = pa[8 * SA + k0 + 4];
        uint32_t ah[4], al[4];
        split_tf32(af0, ah[0], al[0]);
        split_tf32(af1, ah[1], al[1]);
        split_tf32(af2, ah[2], al[2]);
        split_tf32(af3, ah[3], al[3]);

#pragma unroll
        for (int j = 0; j < 8; j++) {
            float bf0 = pb[j * (8 * SA) + k0];
            float bf1 = pb[j * (8 * SA) + k0 + 4];
            uint32_t bh0, bl0, bh1, bl1;
            split_tf32(bf0, bh0, bl0);
            split_tf32(bf1, bh1, bl1);
            mma_tf32(d[j], ah, bh0, bh1);   // Ah*Bh
            mma_tf32(d[j], ah, bl0, bl1);   // Ah*Bl
            mma_tf32(d[j], al, bh0, bh1);   // Al*Bh
        }
    }

    // ---- epilogue: D[16 r][64 l] per warp -> g_atn[e][l][r] ----
    const int r0 = rt + m0 + g;
    const long eb = (long)(e << 6) * R;
#pragma unroll
    for (int j = 0; j < 8; j++) {
        const int l0 = (j << 3) + (t << 1);
        g_atn[eb + (long)(l0    ) * R + r0    ] = d[j][0];
        g_atn[eb + (long)(l0 + 1) * R + r0    ] = d[j][1];
        g_atn[eb + (long)(l0    ) * R + r0 + 8] = d[j][2];
        g_atn[eb + (long)(l0 + 1) * R + r0 + 8] = d[j][3];
    }
}

// ---------------------------------------------------------------------------
// Kernel B: windowed RBF accumulation (unchanged, known-good).
// ---------------------------------------------------------------------------
__global__ __launch_bounds__(256) void rbf_energy(const float* __restrict__ ligc,
                                                  const float* __restrict__ recc) {
    const int l   = blockIdx.x;
    const int rt  = blockIdx.y * RTILE;
    const int tid = threadIdx.x;

    __shared__ float s_a[E][256];
    __shared__ float s_lc[P][3];
    __shared__ float s_red[8][P];

    if (tid < P * 3) {
        int p = tid / 3, cc = tid % 3;
        s_lc[p][cc] = ligc[p * (L * 3) + l * 3 + cc];
    }
#pragma unroll
    for (int e = 0; e < E; e++)
        s_a[e][tid] = g_atn[(e * L + l) * R + rt + tid];
    __syncthreads();

    const int r = rt + tid;
    const float cx = recc[3 * r + 0];
    const float cy = recc[3 * r + 1];
    const float cz = recc[3 * r + 2];

    float acc[P];
#pragma unroll
    for (int p = 0; p < P; p++) {
        float dx = s_lc[p][0] - cx;
        float dy = s_lc[p][1] - cy;
        float dz = s_lc[p][2] - cz;
        // eps added per-coordinate before sum, as in reference: +3*1e-10
        float d2 = fmaf(dx, dx, fmaf(dy, dy, fmaf(dz, dz, 3.0e-10f)));
        float d  = sqrtf(d2);

        int elo = (int)ceilf((d - WIN) * INV_DELTA);
        if (elo < 0) elo = 0;
        int ehi = (int)floorf((d + WIN) * INV_DELTA);
        if (ehi > E - 1) ehi = E - 1;

        float s  = (d - (float)elo * DELTA) * KC;
        float ap = 0.0f;
        for (int e = elo; e <= ehi; e++) {
            float ttt = -s * s;
            float rbf;
            asm("ex2.approx.ftz.f32 %0, %1;" : "=f"(rbf) : "f"(ttt));
            ap = fmaf(s_a[e][tid], rbf, ap);
            s -= DK;
        }
        acc[p] = ap;
    }

#pragma unroll
    for (int p = 0; p < P; p++) {
        float v = acc[p];
#pragma unroll
        for (int off = 16; off; off >>= 1)
            v += __shfl_down_sync(0xffffffffu, v, off);
        if ((tid & 31) == 0) s_red[tid >> 5][p] = v;
    }
    __syncthreads();
    if (tid < P) {
        float v = 0.0f;
#pragma unroll
        for (int w = 0; w < 8; w++) v += s_red[w][tid];
        g_part[(l * NRT + blockIdx.y) * P + tid] = v;
    }
}

// ---------------------------------------------------------------------------
// Kernel C: reduce partials, apply weight/bias
// ---------------------------------------------------------------------------
__global__ __launch_bounds__(256) void finalize_k(const float* __restrict__ w,
                                                  const float* __restrict__ b,
                                                  float* __restrict__ out) {
    const int p    = threadIdx.x >> 5;
    const int lane = threadIdx.x & 31;
    float s = 0.0f;
    for (int k = lane; k < L * NRT; k += 32) s += g_part[k * P + p];
#pragma unroll
    for (int off = 16; off; off >>= 1)
        s += __shfl_down_sync(0xffffffffu, s, off);
    if (lane == 0) out[p] = fmaf(s, *w, *b);
}

// ---------------------------------------------------------------------------
extern "C" void kernel_launch(void* const* d_in, const int* in_sizes, int n_in,
                              void* d_out, int out_size) {
    const float* lig_feat   = (const float*)d_in[0];
    const float* rec_feat   = (const float*)d_in[1];
    const float* lig_coords = (const float*)d_in[2];
    const float* rec_coord  = (const float*)d_in[3];
    const float* weight     = (const float*)d_in[4];
    const float* bias       = (const float*)d_in[5];
    float* out = (float*)d_out;

    const int smem = (128 * SA + 64 * SA) * (int)sizeof(float);   // ~52 KB
    cudaFuncSetAttribute(atn_mma, cudaFuncAttributeMaxDynamicSharedMemorySize, smem);

    atn_mma   <<<dim3(E, NRT_A), 256, smem>>>(lig_feat, rec_feat);
    rbf_energy<<<dim3(L, NRT), 256>>>(lig_coords, rec_coord);
    finalize_k<<<1, 256>>>(weight, bias, out);
}

// round 9
// speedup vs baseline: 1.7797x; 1.2775x over previous
#include <cuda_runtime.h>
#include <math.h>
#include <cstdint>

#define L 64
#define R 4096
#define E 32
#define F 64
#define P 8

// ---- GEMM tiling: per block e fixed, M(r)=128, N(l)=64, K(f)=64 ----
#define MT     128
#define NRT_A  (R / MT)      // 32
#define SW     36            // smem row stride in b32 words (32 data pairs + 4 pad)
                             // lane (g,t): (36g+t)%32 = 4g+t -> conflict-free

// ---- RBF tiling ----
#define RTILE 256
#define NRT   (R / RTILE)    // 16

// RBF constants
#define DELTA      (10.0f / 31.0f)
#define INV_DELTA  (31.0f / 10.0f)
#define KC         3.8435917081166394f   // sqrt(log2 e)/|sigma|, sigma = -0.3125
#define DK         1.2398682929408514f   // DELTA * KC
#define DKSQ       1.5372733816041298f   // DK^2
#define C2R        0.1187050163f         // 2^(-2*DK^2)
#define WIN        2.0f                   // |d-mu| > 2 -> rbf < 2e-18, dropped

// scratch: atn[e][l][r] (33.5 MB, L2-resident) and per-block partials
__device__ float g_atn[E * L * R];
__device__ float g_part[L * NRT * P];

// ---- bf16 helpers -------------------------------------------------------
// pack: high half = bf16(hi_val), low half = bf16(lo_val).
// MMA fragment convention: low 16 bits = even-k element.
__device__ __forceinline__ uint32_t pack_bf16(float hi_val, float lo_val) {
    uint32_t r;
    asm("cvt.rn.bf16x2.f32 %0, %1, %2;" : "=r"(r) : "f"(hi_val), "f"(lo_val));
    return r;
}
// split pair (x -> low half, y -> high half): h = bf16 his, l = bf16 residuals
__device__ __forceinline__ void split_pair(float x, float y,
                                           uint32_t& h, uint32_t& l) {
    h = pack_bf16(y, x);
    float fx = __uint_as_float(h << 16);          // exact f32 of bf16(x)
    float fy = __uint_as_float(h & 0xffff0000u);  // exact f32 of bf16(y)
    l = pack_bf16(y - fy, x - fx);
}
__device__ __forceinline__ void mma_bf16(float* d,
                                         uint32_t a0, uint32_t a1,
                                         uint32_t a2, uint32_t a3,
                                         uint32_t b0, uint32_t b1) {
    asm volatile(
        "mma.sync.aligned.m16n8k16.row.col.f32.bf16.bf16.f32 "
        "{%0,%1,%2,%3}, {%4,%5,%6,%7}, {%8,%9}, {%0,%1,%2,%3};"
        : "+f"(d[0]), "+f"(d[1]), "+f"(d[2]), "+f"(d[3])
        : "r"(a0), "r"(a1), "r"(a2), "r"(a3), "r"(b0), "r"(b1));
}

// ---------------------------------------------------------------------------
// Kernel A: 3xBF16 mma.sync m16n8k16.  atn_t[r,l] = sum_f rec[r,e,f]*lig[l,e,f]
// grid (E, NRT_A), 256 threads (8 warps). Warp w: rows m0=16w..m0+15, all 64 l.
// smem: pre-split bf16-pair tiles rec_hi/lo [128][SW], lig_hi/lo [64][SW].
// word i of a row = {low: f=2i, high: f=2i+1}.
// Fragment maps (PTX m16n8k16 row.col):
//   A: a0=A[g][2t,2t+1]    a1=A[g+8][..]   a2=A[g][2t+8,2t+9]  a3=A[g+8][..]
//      -> words: [t], [8*SW+t], [t+4], [8*SW+t+4]  (+8*ks per K-chunk)
//   B: b0=B[k=2t..][n=g] b1=B[k=2t+8..][n=g] -> words [t], [t+4] of lig row g
//   C: c0=(g,2t) c1=(g,2t+1) c2=(g+8,2t) c3=(g+8,2t+1)
// ---------------------------------------------------------------------------
#define S_RH 0
#define S_RL (128 * SW)            // 4608
#define S_LH (2 * 128 * SW)        // 9216
#define S_LL (2 * 128 * SW + 64 * SW)
#define S_WORDS (2 * 128 * SW + 2 * 64 * SW)   // 13824 words = 54 KB

__global__ __launch_bounds__(256)
void atn_mma(const float* __restrict__ lig, const float* __restrict__ rec) {
    extern __shared__ uint32_t sm[];
    const int e   = blockIdx.x;
    const int rt  = blockIdx.y * MT;
    const int tid = threadIdx.x;

    // ---- load + split rec tile [128 r][64 f] ----
#pragma unroll
    for (int it = 0; it < 8; it++) {
        int idx = tid + (it << 8);           // float4 index
        int row = idx >> 4, f4 = idx & 15;
        float4 v = *(const float4*)(rec + (((rt + row) * E + e) << 6) + (f4 << 2));
        uint32_t h0, l0, h1, l1;
        split_pair(v.x, v.y, h0, l0);
        split_pair(v.z, v.w, h1, l1);
        int base = row * SW + (f4 << 1);
        *(uint2*)(sm + S_RH + base) = make_uint2(h0, h1);
        *(uint2*)(sm + S_RL + base) = make_uint2(l0, l1);
    }
    // ---- load + split lig tile [64 l][64 f] ----
#pragma unroll
    for (int it = 0; it < 4; it++) {
        int idx = tid + (it << 8);
        int row = idx >> 4, f4 = idx & 15;
        float4 v = *(const float4*)(lig + ((row * E + e) << 6) + (f4 << 2));
        uint32_t h0, l0, h1, l1;
        split_pair(v.x, v.y, h0, l0);
        split_pair(v.z, v.w, h1, l1);
        int base = row * SW + (f4 << 1);
        *(uint2*)(sm + S_LH + base) = make_uint2(h0, h1);
        *(uint2*)(sm + S_LL + base) = make_uint2(l0, l1);
    }
    __syncthreads();

    const int wid = tid >> 5;
    const int lid = tid & 31;
    const int g   = lid >> 2;      // group (0..7)
    const int t   = lid & 3;       // thread in group (0..3)
    const int m0  = wid << 4;      // 16-row tile per warp

    float d[8][4];
#pragma unroll
    for (int j = 0; j < 8; j++)
#pragma unroll
        for (int c = 0; c < 4; c++) d[j][c] = 0.0f;

    const uint32_t* pah = sm + S_RH + (m0 + g) * SW + t;
    const uint32_t* pal = sm + S_RL + (m0 + g) * SW + t;
    const uint32_t* pbh = sm + S_LH + g * SW + t;
    const uint32_t* pbl = sm + S_LL + g * SW + t;

#pragma unroll
    for (int ks = 0; ks < 4; ks++) {           // K chunks of 16 f
        const int w = ks << 3;                 // 8 words per chunk
        uint32_t ah0 = pah[w],            ah1 = pah[8 * SW + w];
        uint32_t ah2 = pah[w + 4],        ah3 = pah[8 * SW + w + 4];
        uint32_t al0 = pal[w],            al1 = pal[8 * SW + w];
        uint32_t al2 = pal[w + 4],        al3 = pal[8 * SW + w + 4];

#pragma unroll
        for (int j = 0; j < 8; j++) {          // 8 n-tiles of 8 l
            uint32_t bh0 = pbh[j * (8 * SW) + w];
            uint32_t bh1 = pbh[j * (8 * SW) + w + 4];
            uint32_t bl0 = pbl[j * (8 * SW) + w];
            uint32_t bl1 = pbl[j * (8 * SW) + w + 4];
            mma_bf16(d[j], ah0, ah1, ah2, ah3, bh0, bh1);   // Ah*Bh
            mma_bf16(d[j], ah0, ah1, ah2, ah3, bl0, bl1);   // Ah*Bl
            mma_bf16(d[j], al0, al1, al2, al3, bh0, bh1);   // Al*Bh
        }
    }

    // ---- epilogue: D[16 r][64 l] per warp -> g_atn[e][l][r] ----
    const int r0 = rt + m0 + g;
    const long eb = (long)(e << 6) * R;
#pragma unroll
    for (int j = 0; j < 8; j++) {
        const int l0 = (j << 3) + (t << 1);
        g_atn[eb + (long)(l0    ) * R + r0    ] = d[j][0];
        g_atn[eb + (long)(l0 + 1) * R + r0    ] = d[j][1];
        g_atn[eb + (long)(l0    ) * R + r0 + 8] = d[j][2];
        g_atn[eb + (long)(l0 + 1) * R + r0 + 8] = d[j][3];
    }
}

// ---------------------------------------------------------------------------
// Kernel B: windowed RBF with multiplicative recurrence.
// exp2(-(s-k*DK)^2): f <- f*u, u <- u*C2R.  2 MUFU/pose instead of ~13.
// ---------------------------------------------------------------------------
__global__ __launch_bounds__(256) void rbf_energy(const float* __restrict__ ligc,
                                                  const float* __restrict__ recc) {
    const int l   = blockIdx.x;
    const int rt  = blockIdx.y * RTILE;
    const int tid = threadIdx.x;

    __shared__ float s_a[E][256];
    __shared__ float s_lc[P][3];
    __shared__ float s_red[8][P];

    if (tid < P * 3) {
        int p = tid / 3, cc = tid % 3;
        s_lc[p][cc] = ligc[p * (L * 3) + l * 3 + cc];
    }
#pragma unroll
    for (int e = 0; e < E; e++)
        s_a[e][tid] = g_atn[(e * L + l) * R + rt + tid];
    __syncthreads();

    const int r = rt + tid;
    const float cx = recc[3 * r + 0];
    const float cy = recc[3 * r + 1];
    const float cz = recc[3 * r + 2];

    float acc[P];
#pragma unroll
    for (int p = 0; p < P; p++) {
        float dx = s_lc[p][0] - cx;
        float dy = s_lc[p][1] - cy;
        float dz = s_lc[p][2] - cz;
        // eps added per-coordinate before sum, as in reference: +3*1e-10
        float d2 = fmaf(dx, dx, fmaf(dy, dy, fmaf(dz, dz, 3.0e-10f)));
        float d;
        asm("sqrt.approx.ftz.f32 %0, %1;" : "=f"(d) : "f"(d2));

        int elo = (int)ceilf((d - WIN) * INV_DELTA);
        if (elo < 0) elo = 0;
        int ehi = (int)floorf((d + WIN) * INV_DELTA);
        if (ehi > E - 1) ehi = E - 1;

        float s = (d - (float)elo * DELTA) * KC;
        float f, u;
        {
            float t0 = -s * s;
            asm("ex2.approx.ftz.f32 %0, %1;" : "=f"(f) : "f"(t0));
            float t1 = fmaf(2.0f * DK, s, -DKSQ);
            asm("ex2.approx.ftz.f32 %0, %1;" : "=f"(u) : "f"(t1));
        }
        float ap = 0.0f;
        for (int e = elo; e <= ehi; e++) {
            ap = fmaf(s_a[e][tid], f, ap);
            f *= u;
            u *= C2R;
        }
        acc[p] = ap;
    }

#pragma unroll
    for (int p = 0; p < P; p++) {
        float v = acc[p];
#pragma unroll
        for (int off = 16; off; off >>= 1)
            v += __shfl_down_sync(0xffffffffu, v, off);
        if ((tid & 31) == 0) s_red[tid >> 5][p] = v;
    }
    __syncthreads();
    if (tid < P) {
        float v = 0.0f;
#pragma unroll
        for (int w = 0; w < 8; w++) v += s_red[w][tid];
        g_part[(l * NRT + blockIdx.y) * P + tid] = v;
    }
}

// ---------------------------------------------------------------------------
// Kernel C: reduce partials, apply weight/bias
// ---------------------------------------------------------------------------
__global__ __launch_bounds__(256) void finalize_k(const float* __restrict__ w,
                                                  const float* __restrict__ b,
                                                  float* __restrict__ out) {
    const int p    = threadIdx.x >> 5;
    const int lane = threadIdx.x & 31;
    float s = 0.0f;
    for (int k = lane; k < L * NRT; k += 32) s += g_part[k * P + p];
#pragma unroll
    for (int off = 16; off; off >>= 1)
        s += __shfl_down_sync(0xffffffffu, s, off);
    if (lane == 0) out[p] = fmaf(s, *w, *b);
}

// ---------------------------------------------------------------------------
extern "C" void kernel_launch(void* const* d_in, const int* in_sizes, int n_in,
                              void* d_out, int out_size) {
    const float* lig_feat   = (const float*)d_in[0];
    const float* rec_feat   = (const float*)d_in[1];
    const float* lig_coords = (const float*)d_in[2];
    const float* rec_coord  = (const float*)d_in[3];
    const float* weight     = (const float*)d_in[4];
    const float* bias       = (const float*)d_in[5];
    float* out = (float*)d_out;

    const int smem = S_WORDS * (int)sizeof(uint32_t);   // 55296 B
    cudaFuncSetAttribute(atn_mma, cudaFuncAttributeMaxDynamicSharedMemorySize, smem);

    atn_mma   <<<dim3(E, NRT_A), 256, smem>>>(lig_feat, rec_feat);
    rbf_energy<<<dim3(L, NRT), 256>>>(lig_coords, rec_coord);
    finalize_k<<<1, 256>>>(weight, bias, out);
}

// round 10
// speedup vs baseline: 1.8587x; 1.0444x over previous
#include <cuda_runtime.h>
#include <cuda_fp16.h>
#include <math.h>
#include <cstdint>

#define L 64
#define R 4096
#define E 32
#define F 64
#define P 8

// ---- GEMM tiling: per block e fixed, M(r)=128, N(l)=64, K(f)=64 ----
#define MT     128
#define NRT_A  (R / MT)      // 32
#define SW     36            // smem row stride in b32 words; (36g+t)%32=4g+t conflict-free

// epilogue half-buffer row stride (halfwords): 136 = 17*8, 16B-aligned rows,
// bank = 4*l + r/2 (mod 32) -> 8t + g/2 pattern, conflict-free STS.16
#define HS     136

// ---- RBF tiling ----
#define RTILE 256
#define NRT   (R / RTILE)    // 16

// RBF constants
#define DELTA      (10.0f / 31.0f)
#define INV_DELTA  (31.0f / 10.0f)
#define KC         3.8435917081166394f   // sqrt(log2 e)/|sigma|, sigma = -0.3125
#define DK         1.2398682929408514f   // DELTA * KC
#define DKSQ       1.5372733816041298f   // DK^2
#define C2R        0.1187050163f         // 2^(-2*DK^2)
#define WIN        2.0f                   // |d-mu| > 2 -> rbf < 2e-18, dropped

// scratch: atn[e][l][r] in fp16 (16.75 MB, L2-resident) + per-block partials
__device__ uint4 g_atn_u[E * L * R / 8];   // 16B-aligned half storage
__device__ float g_part[L * NRT * P];

// ---- bf16 helpers -------------------------------------------------------
__device__ __forceinline__ uint32_t pack_bf16(float hi_val, float lo_val) {
    uint32_t r;
    asm("cvt.rn.bf16x2.f32 %0, %1, %2;" : "=r"(r) : "f"(hi_val), "f"(lo_val));
    return r;
}
// split pair (x -> low half, y -> high half): h = bf16 his, l = bf16 residuals
__device__ __forceinline__ void split_pair(float x, float y,
                                           uint32_t& h, uint32_t& l) {
    h = pack_bf16(y, x);
    float fx = __uint_as_float(h << 16);
    float fy = __uint_as_float(h & 0xffff0000u);
    l = pack_bf16(y - fy, x - fx);
}
__device__ __forceinline__ void mma_bf16(float* d,
                                         uint32_t a0, uint32_t a1,
                                         uint32_t a2, uint32_t a3,
                                         uint32_t b0, uint32_t b1) {
    asm volatile(
        "mma.sync.aligned.m16n8k16.row.col.f32.bf16.bf16.f32 "
        "{%0,%1,%2,%3}, {%4,%5,%6,%7}, {%8,%9}, {%0,%1,%2,%3};"
        : "+f"(d[0]), "+f"(d[1]), "+f"(d[2]), "+f"(d[3])
        : "r"(a0), "r"(a1), "r"(a2), "r"(a3), "r"(b0), "r"(b1));
}

// ---------------------------------------------------------------------------
// Kernel A: 3xBF16 mma.sync m16n8k16.  atn_t[r,l] = sum_f rec[r,e,f]*lig[l,e,f]
// grid (E, NRT_A), 256 threads (8 warps as 4(r) x 2(l)); warp tile 32r x 32l.
// smem: pre-split bf16-pair tiles rec_hi/lo [128][SW], lig_hi/lo [64][SW];
// epilogue reuses smem as half buffer [64 l][HS] then coalesced fp16 stores.
// ---------------------------------------------------------------------------
#define S_RH 0
#define S_RL (128 * SW)
#define S_LH (2 * 128 * SW)
#define S_LL (2 * 128 * SW + 64 * SW)
#define S_WORDS (2 * 128 * SW + 2 * 64 * SW)   // 13824 words = 54 KB

__global__ __launch_bounds__(256)
void atn_mma(const float* __restrict__ lig, const float* __restrict__ rec) {
    extern __shared__ uint32_t sm[];
    const int e   = blockIdx.x;
    const int rt  = blockIdx.y * MT;
    const int tid = threadIdx.x;

    // ---- load + split rec tile [128 r][64 f] ----
#pragma unroll
    for (int it = 0; it < 8; it++) {
        int idx = tid + (it << 8);
        int row = idx >> 4, f4 = idx & 15;
        float4 v = *(const float4*)(rec + (((rt + row) * E + e) << 6) + (f4 << 2));
        uint32_t h0, l0, h1, l1;
        split_pair(v.x, v.y, h0, l0);
        split_pair(v.z, v.w, h1, l1);
        int base = row * SW + (f4 << 1);
        *(uint2*)(sm + S_RH + base) = make_uint2(h0, h1);
        *(uint2*)(sm + S_RL + base) = make_uint2(l0, l1);
    }
    // ---- load + split lig tile [64 l][64 f] ----
#pragma unroll
    for (int it = 0; it < 4; it++) {
        int idx = tid + (it << 8);
        int row = idx >> 4, f4 = idx & 15;
        float4 v = *(const float4*)(lig + ((row * E + e) << 6) + (f4 << 2));
        uint32_t h0, l0, h1, l1;
        split_pair(v.x, v.y, h0, l0);
        split_pair(v.z, v.w, h1, l1);
        int base = row * SW + (f4 << 1);
        *(uint2*)(sm + S_LH + base) = make_uint2(h0, h1);
        *(uint2*)(sm + S_LL + base) = make_uint2(l0, l1);
    }
    __syncthreads();

    const int wid = tid >> 5;
    const int lid = tid & 31;
    const int g   = lid >> 2;        // group (0..7)
    const int t   = lid & 3;         // thread in group (0..3)
    const int mb  = (wid & 3) << 5;  // warp r-base (0,32,64,96)
    const int nb  = (wid >> 2) << 5; // warp l-base (0,32)

    float d[2][4][4];
#pragma unroll
    for (int mt = 0; mt < 2; mt++)
#pragma unroll
        for (int j = 0; j < 4; j++)
#pragma unroll
            for (int c = 0; c < 4; c++) d[mt][j][c] = 0.0f;

    const uint32_t* pah = sm + S_RH + (mb + g) * SW + t;
    const uint32_t* pal = sm + S_RL + (mb + g) * SW + t;
    const uint32_t* pbh = sm + S_LH + (nb + g) * SW + t;
    const uint32_t* pbl = sm + S_LL + (nb + g) * SW + t;

#pragma unroll
    for (int ks = 0; ks < 4; ks++) {           // K chunks of 16 f
        const int w = ks << 3;
        uint32_t ah[2][4], al[2][4];
#pragma unroll
        for (int mt = 0; mt < 2; mt++) {
            const int mo = mt * (16 * SW);
            ah[mt][0] = pah[mo + w];          ah[mt][1] = pah[mo + 8 * SW + w];
            ah[mt][2] = pah[mo + w + 4];      ah[mt][3] = pah[mo + 8 * SW + w + 4];
            al[mt][0] = pal[mo + w];          al[mt][1] = pal[mo + 8 * SW + w];
            al[mt][2] = pal[mo + w + 4];      al[mt][3] = pal[mo + 8 * SW + w + 4];
        }
#pragma unroll
        for (int j = 0; j < 4; j++) {          // 4 n8 tiles in 32-l slice
            const int jo = j * (8 * SW);
            uint32_t bh0 = pbh[jo + w], bh1 = pbh[jo + w + 4];
            uint32_t bl0 = pbl[jo + w], bl1 = pbl[jo + w + 4];
#pragma unroll
            for (int mt = 0; mt < 2; mt++) {
                mma_bf16(d[mt][j], ah[mt][0], ah[mt][1], ah[mt][2], ah[mt][3], bh0, bh1);
                mma_bf16(d[mt][j], ah[mt][0], ah[mt][1], ah[mt][2], ah[mt][3], bl0, bl1);
                mma_bf16(d[mt][j], al[mt][0], al[mt][1], al[mt][2], al[mt][3], bh0, bh1);
            }
        }
    }

    // ---- epilogue: transpose through smem, store fp16 coalesced ----
    __syncthreads();                         // done reading tiles
    __half* sm_h = reinterpret_cast<__half*>(sm);
#pragma unroll
    for (int mt = 0; mt < 2; mt++)
#pragma unroll
        for (int j = 0; j < 4; j++) {
            const int l0 = nb + (j << 3) + (t << 1);
            const int r0 = mb + (mt << 4) + g;
            sm_h[ l0      * HS + r0    ] = __float2half(d[mt][j][0]);
            sm_h[(l0 + 1) * HS + r0    ] = __float2half(d[mt][j][1]);
            sm_h[ l0      * HS + r0 + 8] = __float2half(d[mt][j][2]);
            sm_h[(l0 + 1) * HS + r0 + 8] = __float2half(d[mt][j][3]);
        }
    __syncthreads();

    // cooperative writeout: 4 threads per l-row, 16B each, 64B contiguous/row
    {
        __half* ga = reinterpret_cast<__half*>(g_atn_u);
        const int lrow = tid >> 2, q = tid & 3;
        __half* dst = ga + ((long)((e << 6) + lrow)) * R + rt;
        const __half* src = sm_h + lrow * HS;
#pragma unroll
        for (int i = 0; i < 4; i++) {
            int off = (((i << 2) + q) << 3);   // (4i+q)*8 halves
            *(uint4*)(dst + off) = *(const uint4*)(src + off);
        }
    }
}

// ---------------------------------------------------------------------------
// Kernel B: windowed RBF with multiplicative recurrence; fp16 atn stage-in.
// ---------------------------------------------------------------------------
__global__ __launch_bounds__(256) void rbf_energy(const float* __restrict__ ligc,
                                                  const float* __restrict__ recc) {
    const int l   = blockIdx.x;
    const int rt  = blockIdx.y * RTILE;
    const int tid = threadIdx.x;

    __shared__ float s_a[E][256];
    __shared__ float s_lc[P][3];
    __shared__ float s_red[8][P];

    if (tid < P * 3) {
        int p = tid / 3, cc = tid % 3;
        s_lc[p][cc] = ligc[p * (L * 3) + l * 3 + cc];
    }
    {
        const __half* ga = reinterpret_cast<const __half*>(g_atn_u);
#pragma unroll
        for (int e = 0; e < E; e++)
            s_a[e][tid] = __half2float(ga[((long)(e * L + l)) * R + rt + tid]);
    }
    __syncthreads();

    const int r = rt + tid;
    const float cx = recc[3 * r + 0];
    const float cy = recc[3 * r + 1];
    const float cz = recc[3 * r + 2];

    float acc[P];
#pragma unroll
    for (int p = 0; p < P; p++) {
        float dx = s_lc[p][0] - cx;
        float dy = s_lc[p][1] - cy;
        float dz = s_lc[p][2] - cz;
        // eps added per-coordinate before sum, as in reference: +3*1e-10
        float d2 = fmaf(dx, dx, fmaf(dy, dy, fmaf(dz, dz, 3.0e-10f)));
        float d;
        asm("sqrt.approx.ftz.f32 %0, %1;" : "=f"(d) : "f"(d2));

        int elo = (int)ceilf((d - WIN) * INV_DELTA);
        if (elo < 0) elo = 0;
        int ehi = (int)floorf((d + WIN) * INV_DELTA);
        if (ehi > E - 1) ehi = E - 1;

        float s = (d - (float)elo * DELTA) * KC;
        float f, u;
        {
            float t0 = -s * s;
            asm("ex2.approx.ftz.f32 %0, %1;" : "=f"(f) : "f"(t0));
            float t1 = fmaf(2.0f * DK, s, -DKSQ);
            asm("ex2.approx.ftz.f32 %0, %1;" : "=f"(u) : "f"(t1));
        }
        float ap = 0.0f;
        for (int e = elo; e <= ehi; e++) {
            ap = fmaf(s_a[e][tid], f, ap);
            f *= u;
            u *= C2R;
        }
        acc[p] = ap;
    }

#pragma unroll
    for (int p = 0; p < P; p++) {
        float v = acc[p];
#pragma unroll
        for (int off = 16; off; off >>= 1)
            v += __shfl_down_sync(0xffffffffu, v, off);
        if ((tid & 31) == 0) s_red[tid >> 5][p] = v;
    }
    __syncthreads();
    if (tid < P) {
        float v = 0.0f;
#pragma unroll
        for (int w = 0; w < 8; w++) v += s_red[w][tid];
        g_part[(l * NRT + blockIdx.y) * P + tid] = v;
    }
}

// ---------------------------------------------------------------------------
// Kernel C: reduce partials, apply weight/bias
// ---------------------------------------------------------------------------
__global__ __launch_bounds__(256) void finalize_k(const float* __restrict__ w,
                                                  const float* __restrict__ b,
                                                  float* __restrict__ out) {
    const int p    = threadIdx.x >> 5;
    const int lane = threadIdx.x & 31;
    float s = 0.0f;
    for (int k = lane; k < L * NRT; k += 32) s += g_part[k * P + p];
#pragma unroll
    for (int off = 16; off; off >>= 1)
        s += __shfl_down_sync(0xffffffffu, s, off);
    if (lane == 0) out[p] = fmaf(s, *w, *b);
}

// ---------------------------------------------------------------------------
extern "C" void kernel_launch(void* const* d_in, const int* in_sizes, int n_in,
                              void* d_out, int out_size) {
    const float* lig_feat   = (const float*)d_in[0];
    const float* rec_feat   = (const float*)d_in[1];
    const float* lig_coords = (const float*)d_in[2];
    const float* rec_coord  = (const float*)d_in[3];
    const float* weight     = (const float*)d_in[4];
    const float* bias       = (const float*)d_in[5];
    float* out = (float*)d_out;

    const int smem = S_WORDS * (int)sizeof(uint32_t);   // 55296 B
    cudaFuncSetAttribute(atn_mma, cudaFuncAttributeMaxDynamicSharedMemorySize, smem);

    atn_mma   <<<dim3(E, NRT_A), 256, smem>>>(lig_feat, rec_feat);
    rbf_energy<<<dim3(L, NRT), 256>>>(lig_coords, rec_coord);
    finalize_k<<<1, 256>>>(weight, bias, out);
}

// round 11
// speedup vs baseline: 1.9322x; 1.0395x over previous
#include <cuda_runtime.h>
#include <cuda_fp16.h>
#include <math.h>
#include <cstdint>

#define L 64
#define R 4096
#define E 32
#define F 64
#define P 8

// ---- GEMM tiling: per block e fixed, M(r)=128, N(l)=64, K(f)=64 ----
#define MT     128
#define NRT_A  (R / MT)      // 32
#define SW     36            // smem row stride in b32 words; rows land on banks 4g+t

// epilogue half-buffer row stride (halfwords)
#define HS     136

// ---- RBF tiling ----
#define RTILE 256
#define NRT   (R / RTILE)    // 16

// RBF constants
#define DELTA      (10.0f / 31.0f)
#define INV_DELTA  (31.0f / 10.0f)
#define KC         3.8435917081166394f   // sqrt(log2 e)/|sigma|, sigma = -0.3125
#define DK         1.2398682929408514f   // DELTA * KC
#define DKSQ       1.5372733816041298f   // DK^2
#define C2R        0.1187050163f         // 2^(-2*DK^2)
#define WIN        2.0f

// scratch: atn[e][l][r] in fp16 (16.75 MB, L2-resident) + per-block partials
__device__ uint4 g_atn_u[E * L * R / 8];
__device__ float g_part[L * NRT * P];

__device__ __forceinline__ uint32_t s2u(const void* p) {
    uint32_t a;
    asm("{ .reg .u64 t; cvta.to.shared.u64 t, %1; cvt.u32.u64 %0, t; }"
        : "=r"(a) : "l"(p));
    return a;
}

// ---- bf16 helpers -------------------------------------------------------
__device__ __forceinline__ uint32_t pack_bf16(float hi_val, float lo_val) {
    uint32_t r;
    asm("cvt.rn.bf16x2.f32 %0, %1, %2;" : "=r"(r) : "f"(hi_val), "f"(lo_val));
    return r;
}
// split pair (x -> low half, y -> high half): h = bf16 his, l = bf16 residuals
__device__ __forceinline__ void split_pair(float x, float y,
                                           uint32_t& h, uint32_t& l) {
    h = pack_bf16(y, x);
    float fx = __uint_as_float(h << 16);
    float fy = __uint_as_float(h & 0xffff0000u);
    l = pack_bf16(y - fy, x - fx);
}
__device__ __forceinline__ void mma_bf16(float* d,
                                         uint32_t a0, uint32_t a1,
                                         uint32_t a2, uint32_t a3,
                                         uint32_t b0, uint32_t b1) {
    asm volatile(
        "mma.sync.aligned.m16n8k16.row.col.f32.bf16.bf16.f32 "
        "{%0,%1,%2,%3}, {%4,%5,%6,%7}, {%8,%9}, {%0,%1,%2,%3};"
        : "+f"(d[0]), "+f"(d[1]), "+f"(d[2]), "+f"(d[3])
        : "r"(a0), "r"(a1), "r"(a2), "r"(a3), "r"(b0), "r"(b1));
}
__device__ __forceinline__ void ldsm_x4(uint32_t* r, uint32_t addr) {
    asm volatile("ldmatrix.sync.aligned.m8n8.x4.shared.b16 {%0,%1,%2,%3}, [%4];"
        : "=r"(r[0]), "=r"(r[1]), "=r"(r[2]), "=r"(r[3]) : "r"(addr));
}

// ---------------------------------------------------------------------------
// Kernel A: 3xBF16 mma.sync m16n8k16 with ldmatrix fragment loads.
// grid (E, NRT_A), 256 threads (8 warps as 4(r) x 2(l)); warp tile 32r x 32l.
// ---------------------------------------------------------------------------
#define S_RH 0
#define S_RL (128 * SW)
#define S_LH (2 * 128 * SW)
#define S_LL (2 * 128 * SW + 64 * SW)
#define S_WORDS (2 * 128 * SW + 2 * 64 * SW)   // 13824 words = 54 KB

__global__ __launch_bounds__(256)
void atn_mma(const float* __restrict__ lig, const float* __restrict__ rec) {
    extern __shared__ uint32_t sm[];
    const int e   = blockIdx.x;
    const int rt  = blockIdx.y * MT;
    const int tid = threadIdx.x;

    // ---- load + split rec tile [128 r][64 f] ----
#pragma unroll
    for (int it = 0; it < 8; it++) {
        int idx = tid + (it << 8);
        int row = idx >> 4, f4 = idx & 15;
        float4 v = *(const float4*)(rec + (((rt + row) * E + e) << 6) + (f4 << 2));
        uint32_t h0, l0, h1, l1;
        split_pair(v.x, v.y, h0, l0);
        split_pair(v.z, v.w, h1, l1);
        int base = row * SW + (f4 << 1);
        *(uint2*)(sm + S_RH + base) = make_uint2(h0, h1);
        *(uint2*)(sm + S_RL + base) = make_uint2(l0, l1);
    }
    // ---- load + split lig tile [64 l][64 f] ----
#pragma unroll
    for (int it = 0; it < 4; it++) {
        int idx = tid + (it << 8);
        int row = idx >> 4, f4 = idx & 15;
        float4 v = *(const float4*)(lig + ((row * E + e) << 6) + (f4 << 2));
        uint32_t h0, l0, h1, l1;
        split_pair(v.x, v.y, h0, l0);
        split_pair(v.z, v.w, h1, l1);
        int base = row * SW + (f4 << 1);
        *(uint2*)(sm + S_LH + base) = make_uint2(h0, h1);
        *(uint2*)(sm + S_LL + base) = make_uint2(l0, l1);
    }
    __syncthreads();

    const int wid = tid >> 5;
    const int lid = tid & 31;
    const int g   = lid >> 2;        // group (0..7)
    const int t   = lid & 3;         // thread in group (0..3)
    const int mb  = (wid & 3) << 5;  // warp r-base (0,32,64,96)
    const int nb  = (wid >> 2) << 5; // warp l-base (0,32)

    // ldmatrix lane-group addressing
    const int i8 = lid & 7;
    const int q  = lid >> 3;
    const uint32_t sb = s2u(sm);

    uint32_t a_h[2], a_l[2], b_h[2], b_l[2];
#pragma unroll
    for (int mt = 0; mt < 2; mt++) {
        // matrices: (rows m0..m0+7 @w), (rows+8 @w), (rows @w+4), (rows+8 @w+4)
        int row = mb + (mt << 4) + ((q & 1) << 3) + i8;
        uint32_t off = (uint32_t)(row * SW + ((q >> 1) << 2)) << 2;
        a_h[mt] = sb + (S_RH << 2) + off;
        a_l[mt] = sb + (S_RL << 2) + off;
    }
#pragma unroll
    for (int jp = 0; jp < 2; jp++) {
        // matrices: (j0 rows @w), (j0 rows @w+4), (j1 rows @w), (j1 rows @w+4)
        int row = nb + (jp << 4) + ((q >> 1) << 3) + i8;
        uint32_t off = (uint32_t)(row * SW + ((q & 1) << 2)) << 2;
        b_h[jp] = sb + (S_LH << 2) + off;
        b_l[jp] = sb + (S_LL << 2) + off;
    }

    float d[2][4][4];
#pragma unroll
    for (int mt = 0; mt < 2; mt++)
#pragma unroll
        for (int j = 0; j < 4; j++)
#pragma unroll
            for (int c = 0; c < 4; c++) d[mt][j][c] = 0.0f;

#pragma unroll
    for (int ks = 0; ks < 4; ks++) {           // K chunks of 16 f
        const uint32_t wb = (uint32_t)ks << 5; // 32 bytes per chunk
        uint32_t AH[2][4], AL[2][4], BH[2][4], BL[2][4];
        ldsm_x4(AH[0], a_h[0] + wb);  ldsm_x4(AH[1], a_h[1] + wb);
        ldsm_x4(AL[0], a_l[0] + wb);  ldsm_x4(AL[1], a_l[1] + wb);
        ldsm_x4(BH[0], b_h[0] + wb);  ldsm_x4(BH[1], b_h[1] + wb);
        ldsm_x4(BL[0], b_l[0] + wb);  ldsm_x4(BL[1], b_l[1] + wb);

#pragma unroll
        for (int jp = 0; jp < 2; jp++)
#pragma unroll
            for (int jj = 0; jj < 2; jj++) {
                const int j = (jp << 1) + jj;
                uint32_t bh0 = BH[jp][jj << 1], bh1 = BH[jp][(jj << 1) + 1];
                uint32_t bl0 = BL[jp][jj << 1], bl1 = BL[jp][(jj << 1) + 1];
#pragma unroll
                for (int mt = 0; mt < 2; mt++) {
                    mma_bf16(d[mt][j], AH[mt][0], AH[mt][1], AH[mt][2], AH[mt][3], bh0, bh1);
                    mma_bf16(d[mt][j], AH[mt][0], AH[mt][1], AH[mt][2], AH[mt][3], bl0, bl1);
                    mma_bf16(d[mt][j], AL[mt][0], AL[mt][1], AL[mt][2], AL[mt][3], bh0, bh1);
                }
            }
    }

    // ---- epilogue: transpose through smem, store fp16 coalesced ----
    __syncthreads();
    __half* sm_h = reinterpret_cast<__half*>(sm);
#pragma unroll
    for (int mt = 0; mt < 2; mt++)
#pragma unroll
        for (int j = 0; j < 4; j++) {
            const int l0 = nb + (j << 3) + (t << 1);
            const int r0 = mb + (mt << 4) + g;
            sm_h[ l0      * HS + r0    ] = __float2half(d[mt][j][0]);
            sm_h[(l0 + 1) * HS + r0    ] = __float2half(d[mt][j][1]);
            sm_h[ l0      * HS + r0 + 8] = __float2half(d[mt][j][2]);
            sm_h[(l0 + 1) * HS + r0 + 8] = __float2half(d[mt][j][3]);
        }
    __syncthreads();

    // cooperative writeout: 4 threads per l-row, 16B each
    {
        __half* ga = reinterpret_cast<__half*>(g_atn_u);
        const int lrow = tid >> 2, qq = tid & 3;
        __half* dst = ga + ((long)((e << 6) + lrow)) * R + rt;
        const __half* src = sm_h + lrow * HS;
#pragma unroll
        for (int i = 0; i < 4; i++) {
            int off = (((i << 2) + qq) << 3);
            *(uint4*)(dst + off) = *(const uint4*)(src + off);
        }
    }
}

// ---------------------------------------------------------------------------
// Kernel B: windowed RBF with multiplicative recurrence; vectorized fp16 stage.
// ---------------------------------------------------------------------------
__global__ __launch_bounds__(256) void rbf_energy(const float* __restrict__ ligc,
                                                  const float* __restrict__ recc) {
    const int l   = blockIdx.x;
    const int rt  = blockIdx.y * RTILE;
    const int tid = threadIdx.x;

    __shared__ float s_a[E][256];
    __shared__ float s_lc[P][3];
    __shared__ float s_red[8][P];

    if (tid < P * 3) {
        int p = tid / 3, cc = tid % 3;
        s_lc[p][cc] = ligc[p * (L * 3) + l * 3 + cc];
    }
    {
        const __half* ga = reinterpret_cast<const __half*>(g_atn_u);
#pragma unroll
        for (int it = 0; it < 16; it++) {
            int s = tid + (it << 8);
            int e = s >> 7, rr = (s & 127) << 1;
            __half2 v = *(const __half2*)(ga + ((long)(e * L + l)) * R + rt + rr);
            float2 f = __half22float2(v);
            s_a[e][rr]     = f.x;
            s_a[e][rr + 1] = f.y;
        }
    }
    __syncthreads();

    const int r = rt + tid;
    const float cx = recc[3 * r + 0];
    const float cy = recc[3 * r + 1];
    const float cz = recc[3 * r + 2];

    float acc[P];
#pragma unroll
    for (int p = 0; p < P; p++) {
        float dx = s_lc[p][0] - cx;
        float dy = s_lc[p][1] - cy;
        float dz = s_lc[p][2] - cz;
        // eps added per-coordinate before sum, as in reference: +3*1e-10
        float d2 = fmaf(dx, dx, fmaf(dy, dy, fmaf(dz, dz, 3.0e-10f)));
        float d;
        asm("sqrt.approx.ftz.f32 %0, %1;" : "=f"(d) : "f"(d2));

        int elo = (int)ceilf((d - WIN) * INV_DELTA);
        if (elo < 0) elo = 0;
        int ehi = (int)floorf((d + WIN) * INV_DELTA);
        if (ehi > E - 1) ehi = E - 1;

        float s = (d - (float)elo * DELTA) * KC;
        float f, u;
        {
            float t0 = -s * s;
            asm("ex2.approx.ftz.f32 %0, %1;" : "=f"(f) : "f"(t0));
            float t1 = fmaf(2.0f * DK, s, -DKSQ);
            asm("ex2.approx.ftz.f32 %0, %1;" : "=f"(u) : "f"(t1));
        }
        float ap = 0.0f;
        for (int e = elo; e <= ehi; e++) {
            ap = fmaf(s_a[e][tid], f, ap);
            f *= u;
            u *= C2R;
        }
        acc[p] = ap;
    }

#pragma unroll
    for (int p = 0; p < P; p++) {
        float v = acc[p];
#pragma unroll
        for (int off = 16; off; off >>= 1)
            v += __shfl_down_sync(0xffffffffu, v, off);
        if ((tid & 31) == 0) s_red[tid >> 5][p] = v;
    }
    __syncthreads();
    if (tid < P) {
        float v = 0.0f;
#pragma unroll
        for (int w = 0; w < 8; w++) v += s_red[w][tid];
        g_part[(l * NRT + blockIdx.y) * P + tid] = v;
    }
}

// ---------------------------------------------------------------------------
// Kernel C: reduce partials, apply weight/bias
// ---------------------------------------------------------------------------
__global__ __launch_bounds__(256) void finalize_k(const float* __restrict__ w,
                                                  const float* __restrict__ b,
                                                  float* __restrict__ out) {
    const int p    = threadIdx.x >> 5;
    const int lane = threadIdx.x & 31;
    float s = 0.0f;
    for (int k = lane; k < L * NRT; k += 32) s += g_part[k * P + p];
#pragma unroll
    for (int off = 16; off; off >>= 1)
        s += __shfl_down_sync(0xffffffffu, s, off);
    if (lane == 0) out[p] = fmaf(s, *w, *b);
}

// ---------------------------------------------------------------------------
extern "C" void kernel_launch(void* const* d_in, const int* in_sizes, int n_in,
                              void* d_out, int out_size) {
    const float* lig_feat   = (const float*)d_in[0];
    const float* rec_feat   = (const float*)d_in[1];
    const float* lig_coords = (const float*)d_in[2];
    const float* rec_coord  = (const float*)d_in[3];
    const float* weight     = (const float*)d_in[4];
    const float* bias       = (const float*)d_in[5];
    float* out = (float*)d_out;

    const int smem = S_WORDS * (int)sizeof(uint32_t);   // 55296 B
    cudaFuncSetAttribute(atn_mma, cudaFuncAttributeMaxDynamicSharedMemorySize, smem);

    atn_mma   <<<dim3(E, NRT_A), 256, smem>>>(lig_feat, rec_feat);
    rbf_energy<<<dim3(L, NRT), 256>>>(lig_coords, rec_coord);
    finalize_k<<<1, 256>>>(weight, bias, out);
}